// round 15
// baseline (speedup 1.0000x reference)
#include <cuda_runtime.h>

#define TT   256
#define BB   1024
#define NN   32
#define HH   64
#define RR   8
#define NBLK 128
#define NTHR 256
#define SMEM_FLOATS 52800
#define SMEM_BYTES  (SMEM_FLOATS * 4)

typedef unsigned long long u64;

__device__ float gMsumInv[TT];
__device__ float gXloss[NBLK];
__device__ float gYsum[NBLK];
__device__ float gTsum[NBLK];

__device__ __forceinline__ float sigmf(float x) { return 1.0f / (1.0f + __expf(-x)); }
__device__ __forceinline__ float tanhfast(float x) { return 2.0f / (1.0f + __expf(-2.0f * x)) - 1.0f; }

#define PACK2(dst, lo, hi) \
    asm("mov.b64 %0, {%1, %2};" : "=l"(dst) : "r"(lo), "r"(hi))
#define UNPACK2(lo, hi, src) \
    asm("mov.b64 {%0, %1}, %2;" : "=r"(lo), "=r"(hi) : "l"(src))
#define FMA2(d, a, b, c) \
    asm("fma.rn.f32x2 %0, %1, %2, %3;" : "=l"(d) : "l"(a), "l"(b), "l"(c))
#define ADD2(d, a, b) \
    asm("add.rn.f32x2 %0, %1, %2;" : "=l"(d) : "l"(a), "l"(b))
#define PAIR_BAR(id) \
    asm volatile("bar.sync %0, 64;" :: "r"(id) : "memory")

__device__ __forceinline__ u64 dupf(float v) {
    u64 r; unsigned int u = __float_as_uint(v); PACK2(r, u, u); return r;
}
__device__ __forceinline__ float lo_f(u64 v) {
    unsigned int a, b; UNPACK2(a, b, v); return __uint_as_float(a);
}
__device__ __forceinline__ float hi_f(u64 v) {
    unsigned int a, b; UNPACK2(a, b, v); return __uint_as_float(b);
}

// ---------------------------------------------------------------------------
// K1: per-timestep batch-global mask sum -> 1/(sum+eps)
// ---------------------------------------------------------------------------
__global__ void k_msum(const float* __restrict__ masks) {
    const int t = blockIdx.x;
    const float* p = masks + (size_t)t * NN;
    float s = 0.f;
    for (int i = threadIdx.x; i < BB * NN; i += blockDim.x) {
        int b = i >> 5, n = i & 31;
        s += p[(size_t)b * (TT * NN) + n];
    }
#pragma unroll
    for (int o = 16; o; o >>= 1) s += __shfl_xor_sync(0xffffffffu, s, o);
    __shared__ float red[8];
    if ((threadIdx.x & 31) == 0) red[threadIdx.x >> 5] = s;
    __syncthreads();
    if (threadIdx.x == 0) {
        float tot = 0.f;
#pragma unroll
        for (int i = 0; i < 8; i++) tot += red[i];
        gMsumInv[t] = 1.0f / (tot + 1e-5f);
    }
}

// ---------------------------------------------------------------------------
// K2: persistent recurrence. 128 CTAs x 256 threads (8 warps).
// Warp pair {2p, 2p+1} co-owns rows (2p, 2p+1) with REPLICATED h/c state:
// small segments computed redundantly per-warp (full latency hiding at
// 2 warps/SMSP); gates GEMM split by k (even warp = W_ih half incl. bias,
// odd warp = W_hh half), partials exchanged via smem + named pair barrier,
// combined with commutative ADD2 -> bitwise-identical state in both warps.
// ---------------------------------------------------------------------------
__global__ void __launch_bounds__(NTHR, 1)
k_main(const float* __restrict__ values, const float* __restrict__ masks,
       const float* __restrict__ deltas, const float* __restrict__ labels,
       const float* __restrict__ is_train,
       const float* __restrict__ td_h_W, const float* __restrict__ td_h_b,
       const float* __restrict__ td_x_W, const float* __restrict__ td_x_b,
       const float* __restrict__ hist_W, const float* __restrict__ hist_b,
       const float* __restrict__ feat_W, const float* __restrict__ feat_b,
       const float* __restrict__ wc_W,   const float* __restrict__ wc_b,
       const float* __restrict__ W_ih,   const float* __restrict__ W_hh,
       const float* __restrict__ b_ih,   const float* __restrict__ b_hh,
       const float* __restrict__ out_W,  const float* __restrict__ out_b,
       float* __restrict__ out_pred, float* __restrict__ out_imp)
{
    extern __shared__ float sm[];
    float* sWih2  = sm;              // [64 k][4 gate][32 lane] x2 : cols (2l, 2l+1)
    float* sWhh2  = sWih2  + 16384;
    float* sWth2  = sWhh2  + 16384;  // [32 n][32 lane] x2
    float* sWhi2  = sWth2  + 2048;   // [32 jp][32 n] x2
    float* sWfe2  = sWhi2  + 2048;   // [16 kp][32 n] x2, diag zero
    float* sWwc2  = sWfe2  + 1024;   // [32 kp][32 n] x2
    float* sBth   = sWwc2  + 2048;   // 64
    float* sBg    = sBth   + 64;     // 256
    float* sOutW  = sBg    + 256;    // 64
    float* sTdxD  = sOutW  + 64;     // 32
    float* sTdxB  = sTdxD  + 32;     // 32
    float* sBhist = sTdxB  + 32;     // 32
    float* sBfeat = sBhist + 32;     // 32
    float* sBwc   = sBfeat + 32;     // 32
    float* sRed   = sBwc   + 32;     // 32
    float* sWs    = sRed   + 32;     // 8 warps x 1024 floats workspace
    float* sExch  = sWs    + 8192;   // 8 warps x 512 floats gate-partial exchange

    const int tid = threadIdx.x;
    const int b0  = blockIdx.x * RR;

    // ---- stage weights (paired layouts) ----
    for (int i = tid; i < 16384; i += NTHR) {
        int e = i & 1, l = (i >> 1) & 31, g = (i >> 6) & 3, k = i >> 8;
        int col = g * 64 + 2 * l + e;
        sWih2[i] = W_ih[col * 64 + k];
        sWhh2[i] = W_hh[col * 64 + k];
    }
    for (int i = tid; i < 2048; i += NTHR) {
        int e = i & 1, l = (i >> 1) & 31, n = i >> 6;
        sWth2[i] = td_h_W[(2 * l + e) * NN + n];
    }
    for (int i = tid; i < 2048; i += NTHR) {
        int e = i & 1, n = (i >> 1) & 31, jp = i >> 6;
        sWhi2[i] = hist_W[n * HH + 2 * jp + e];
    }
    for (int i = tid; i < 1024; i += NTHR) {
        int e = i & 1, n = (i >> 1) & 31, kp = i >> 6;
        int k = 2 * kp + e;
        sWfe2[i] = (k == n) ? 0.0f : feat_W[n * NN + k];
    }
    for (int i = tid; i < 2048; i += NTHR) {
        int e = i & 1, n = (i >> 1) & 31, kp = i >> 6;
        sWwc2[i] = wc_W[n * (2 * NN) + 2 * kp + e];
    }
    if (tid < 64) { sBth[tid] = td_h_b[tid]; sOutW[tid] = out_W[tid]; }
    if (tid < 256) sBg[tid] = b_ih[tid] + b_hh[tid];
    if (tid < 32) {
        sTdxD[tid] = td_x_W[tid * NN + tid]; sTdxB[tid] = td_x_b[tid];
        sBhist[tid] = hist_b[tid]; sBfeat[tid] = feat_b[tid]; sBwc[tid] = wc_b[tid];
    }
    __syncthreads();

    const int lane = tid & 31, wid = tid >> 5;
    const int pair = wid >> 1;
    const int isEven = ((wid & 1) == 0);
    const int barId = 1 + pair;                  // named barrier ids 1..4
    const int rowA = 2 * pair, rowB = 2 * pair + 1;

    float* ws  = sWs + wid * 1024;               // per-WARP workspace (both rows)
    float* wsA = ws;
    float* wsB = ws + 512;
    float* dDupA = wsA;         float* dDupB = wsB;
    float* mRowA = wsA + 64;    float* mRowB = wsB + 64;
    float* xcRowA = wsA + 96;   float* xcRowB = wsB + 96;
    float* gxRowA = wsA + 128;  float* gxRowB = wsB + 128;
    float* hPairA = wsA + 160;  float* hPairB = wsB + 160;
    float* inpDupA = wsA + 224; float* inpDupB = wsB + 224;
    float* hDupA = wsA + 352;   float* hDupB = wsB + 352;

    float* myEx = sExch + wid * 512;             // my 8 u64 partials (per lane)
    float* prEx = sExch + (wid ^ 1) * 512;       // partner's

    float hA0 = 0.f, hA1 = 0.f, cA0 = 0.f, cA1 = 0.f;   // replicated state
    float hB0 = 0.f, hB1 = 0.f, cB0 = 0.f, cB1 = 0.f;
    float lossAcc = 0.f;

    const size_t rowBaseA = (size_t)(b0 + rowA) * TT * NN + lane;
    const size_t rowBaseB = (size_t)(b0 + rowB) * TT * NN + lane;
    float xA = values[rowBaseA], mA = masks[rowBaseA], dA = deltas[rowBaseA];
    float xB = values[rowBaseB], mB = masks[rowBaseB], dB = deltas[rowBaseB];
    float inv_ms = gMsumInv[0];

    const u64* wthU = (const u64*)sWth2;
    const u64* whiU = (const u64*)sWhi2;
    const u64* wfeU = (const u64*)sWfe2;
    const u64* wwcU = (const u64*)sWwc2;
    const u64* wihU = (const u64*)sWih2;
    const u64* whhU = (const u64*)sWhh2;
    const u64* ddAU = (const u64*)dDupA;  const u64* ddBU = (const u64*)dDupB;
    const u64* hpAU = (const u64*)hPairA; const u64* hpBU = (const u64*)hPairB;
    const u64* xcAU = (const u64*)xcRowA; const u64* xcBU = (const u64*)xcRowB;
    const u64* gxAU = (const u64*)gxRowA; const u64* gxBU = (const u64*)gxRowB;
    const u64* mAU  = (const u64*)mRowA;  const u64* mBU  = (const u64*)mRowB;
    const u64* ipAU = (const u64*)inpDupA; const u64* ipBU = (const u64*)inpDupB;
    const u64* hdAU = (const u64*)hDupA;   const u64* hdBU = (const u64*)hDupB;

    for (int t = 0; t < TT; t++) {
        const size_t offA = rowBaseA + (size_t)t * NN;
        const size_t offB = rowBaseB + (size_t)t * NN;

        *(u64*)(dDupA + 2 * lane) = dupf(dA); mRowA[lane] = mA;
        *(u64*)(dDupB + 2 * lane) = dupf(dB); mRowB[lane] = mB;
        __syncwarp();  // W1

        // ---- gamma_h + decay (redundant in both warps; identical results) ----
        {
            u64 a0 = *(const u64*)(sBth + 2 * lane), a1 = 0ull;
            u64 b0v = a0, b1 = 0ull;
#pragma unroll 8
            for (int n = 0; n < 32; n += 2) {
                u64 w0 = wthU[n * 32 + lane], w1 = wthU[(n + 1) * 32 + lane];
                FMA2(a0, w0, ddAU[n], a0);   FMA2(a1, w1, ddAU[n + 1], a1);
                FMA2(b0v, w0, ddBU[n], b0v); FMA2(b1, w1, ddBU[n + 1], b1);
            }
            ADD2(a0, a0, a1); ADD2(b0v, b0v, b1);
            hA0 *= __expf(-fmaxf(lo_f(a0), 0.f));
            hA1 *= __expf(-fmaxf(hi_f(a0), 0.f));
            hB0 *= __expf(-fmaxf(lo_f(b0v), 0.f));
            hB1 *= __expf(-fmaxf(hi_f(b0v), 0.f));
            u64 hp;
            PACK2(hp, __float_as_uint(hA0), __float_as_uint(hA1));
            *(u64*)(hPairA + 2 * lane) = hp;
            PACK2(hp, __float_as_uint(hB0), __float_as_uint(hB1));
            *(u64*)(hPairB + 2 * lane) = hp;
            *(u64*)(hDupA + 4 * lane)     = dupf(hA0);
            *(u64*)(hDupA + 4 * lane + 2) = dupf(hA1);
            *(u64*)(hDupB + 4 * lane)     = dupf(hB0);
            *(u64*)(hDupB + 4 * lane + 2) = dupf(hB1);
        }
        __syncwarp();  // W2

        // ---- x_h / x_c / gamma_x (redundant) ----
        float x_hA, e1A, x_hB, e1B;
        {
            u64 a0 = 0ull, a1 = 0ull, b0v = 0ull, b1 = 0ull;
#pragma unroll 8
            for (int jp = 0; jp < 32; jp += 2) {
                u64 w0 = whiU[jp * 32 + lane], w1 = whiU[(jp + 1) * 32 + lane];
                FMA2(a0, w0, hpAU[jp], a0);   FMA2(a1, w1, hpAU[jp + 1], a1);
                FMA2(b0v, w0, hpBU[jp], b0v); FMA2(b1, w1, hpBU[jp + 1], b1);
            }
            ADD2(a0, a0, a1); ADD2(b0v, b0v, b1);
            const float bh = sBhist[lane];
            x_hA = lo_f(a0) + hi_f(a0) + bh;
            x_hB = lo_f(b0v) + hi_f(b0v) + bh;
            xcRowA[lane] = fmaf(mA, xA - x_hA, x_hA);
            xcRowB[lane] = fmaf(mB, xB - x_hB, x_hB);
            const float td = sTdxD[lane], tb = sTdxB[lane];
            gxRowA[lane] = __expf(-fmaxf(fmaf(dA, td, tb), 0.f));
            gxRowB[lane] = __expf(-fmaxf(fmaf(dB, td, tb), 0.f));
            e1A = fabsf(xA - x_hA);
            e1B = fabsf(xB - x_hB);
        }
        __syncwarp();  // W3

        // ---- z_h, alpha, c_h, c_c, loss, imputation (redundant) ----
        {
            u64 zA = 0ull, zB = 0ull;
#pragma unroll 8
            for (int kp = 0; kp < 16; kp++) {
                u64 wv = wfeU[kp * 32 + lane];
                FMA2(zA, wv, xcAU[kp], zA);
                FMA2(zB, wv, xcBU[kp], zB);
            }
            const float bf = sBfeat[lane];
            float zAv = lo_f(zA) + hi_f(zA) + bf;
            float zBv = lo_f(zB) + hi_f(zB) + bf;

            u64 aA = 0ull, aB = 0ull;
#pragma unroll 8
            for (int kp = 0; kp < 16; kp++) {
                u64 w0 = wwcU[kp * 32 + lane];
                u64 w1 = wwcU[(16 + kp) * 32 + lane];
                FMA2(aA, w0, gxAU[kp], aA); FMA2(aA, w1, mAU[kp], aA);
                FMA2(aB, w0, gxBU[kp], aB); FMA2(aB, w1, mBU[kp], aB);
            }
            const float bw = sBwc[lane];
            float alA = lo_f(aA) + hi_f(aA) + bw;
            float alB = lo_f(aB) + hi_f(aB) + bw;

            float chA = fmaf(alA, zAv - x_hA, x_hA);
            float ccA = fmaf(mA, xA - chA, chA);
            float chB = fmaf(alB, zBv - x_hB, x_hB);
            float ccB = fmaf(mB, xB - chB, chB);
            lossAcc = fmaf((e1A + fabsf(xA - zAv) + fabsf(xA - chA)) * mA, inv_ms, lossAcc);
            lossAcc = fmaf((e1B + fabsf(xB - zBv) + fabsf(xB - chB)) * mB, inv_ms, lossAcc);
            if (isEven) {
                out_imp[offA] = ccA;
                out_imp[offB] = ccB;
            }
            *(u64*)(inpDupA + 2 * lane)      = dupf(ccA);
            *(u64*)(inpDupA + 64 + 2 * lane) = dupf(mA);
            *(u64*)(inpDupB + 2 * lane)      = dupf(ccB);
            *(u64*)(inpDupB + 64 + 2 * lane) = dupf(mB);
        }
        __syncwarp();  // W4

        // ---- prefetch t+1 (redundant LDG; hides behind gates) ----
        {
            const int tn = (t + 1 < TT) ? (t + 1) : t;
            const size_t oA = rowBaseA + (size_t)tn * NN;
            const size_t oB = rowBaseB + (size_t)tn * NN;
            xA = values[oA]; mA = masks[oA]; dA = deltas[oA];
            xB = values[oB]; mB = masks[oB]; dB = deltas[oB];
            inv_ms = gMsumInv[tn];
        }

        // ---- gates: split-K across the warp pair ----
        {
            u64 pIA, pFA, pGA, pOA, pIB, pFB, pGB, pOB;
            if (isEven) {
                pIA = *(const u64*)(sBg + 2 * lane);
                pFA = *(const u64*)(sBg + 64 + 2 * lane);
                pGA = *(const u64*)(sBg + 128 + 2 * lane);
                pOA = *(const u64*)(sBg + 192 + 2 * lane);
                pIB = pIA; pFB = pFA; pGB = pGA; pOB = pOA;
#pragma unroll 16
                for (int k = 0; k < 64; k++) {
                    u64 wI = wihU[(k * 4 + 0) * 32 + lane];
                    u64 wF = wihU[(k * 4 + 1) * 32 + lane];
                    u64 wG = wihU[(k * 4 + 2) * 32 + lane];
                    u64 wO = wihU[(k * 4 + 3) * 32 + lane];
                    u64 actA = ipAU[k], actB = ipBU[k];
                    FMA2(pIA, wI, actA, pIA); FMA2(pIB, wI, actB, pIB);
                    FMA2(pFA, wF, actA, pFA); FMA2(pFB, wF, actB, pFB);
                    FMA2(pGA, wG, actA, pGA); FMA2(pGB, wG, actB, pGB);
                    FMA2(pOA, wO, actA, pOA); FMA2(pOB, wO, actB, pOB);
                }
            } else {
                pIA = pFA = pGA = pOA = 0ull;
                pIB = pFB = pGB = pOB = 0ull;
#pragma unroll 16
                for (int k = 0; k < 64; k++) {
                    u64 wI = whhU[(k * 4 + 0) * 32 + lane];
                    u64 wF = whhU[(k * 4 + 1) * 32 + lane];
                    u64 wG = whhU[(k * 4 + 2) * 32 + lane];
                    u64 wO = whhU[(k * 4 + 3) * 32 + lane];
                    u64 actA = hdAU[k], actB = hdBU[k];
                    FMA2(pIA, wI, actA, pIA); FMA2(pIB, wI, actB, pIB);
                    FMA2(pFA, wF, actA, pFA); FMA2(pFB, wF, actB, pFB);
                    FMA2(pGA, wG, actA, pGA); FMA2(pGB, wG, actB, pGB);
                    FMA2(pOA, wO, actA, pOA); FMA2(pOB, wO, actB, pOB);
                }
            }
            // exchange partials with partner warp
            *(u64*)(myEx + 0 * 64 + 2 * lane) = pIA;
            *(u64*)(myEx + 1 * 64 + 2 * lane) = pFA;
            *(u64*)(myEx + 2 * 64 + 2 * lane) = pGA;
            *(u64*)(myEx + 3 * 64 + 2 * lane) = pOA;
            *(u64*)(myEx + 4 * 64 + 2 * lane) = pIB;
            *(u64*)(myEx + 5 * 64 + 2 * lane) = pFB;
            *(u64*)(myEx + 6 * 64 + 2 * lane) = pGB;
            *(u64*)(myEx + 7 * 64 + 2 * lane) = pOB;
            PAIR_BAR(barId);   // partner's partials visible (bar drains STS)
            u64 qIA = *(const u64*)(prEx + 0 * 64 + 2 * lane);
            u64 qFA = *(const u64*)(prEx + 1 * 64 + 2 * lane);
            u64 qGA = *(const u64*)(prEx + 2 * 64 + 2 * lane);
            u64 qOA = *(const u64*)(prEx + 3 * 64 + 2 * lane);
            u64 qIB = *(const u64*)(prEx + 4 * 64 + 2 * lane);
            u64 qFB = *(const u64*)(prEx + 5 * 64 + 2 * lane);
            u64 qGB = *(const u64*)(prEx + 6 * 64 + 2 * lane);
            u64 qOB = *(const u64*)(prEx + 7 * 64 + 2 * lane);
            ADD2(pIA, pIA, qIA); ADD2(pFA, pFA, qFA);    // fp add commutative ->
            ADD2(pGA, pGA, qGA); ADD2(pOA, pOA, qOA);    // identical in both warps
            ADD2(pIB, pIB, qIB); ADD2(pFB, pFB, qFB);
            ADD2(pGB, pGB, qGB); ADD2(pOB, pOB, qOB);
            PAIR_BAR(barId);   // both consumed -> exchange bufs reusable at t+1

            cA0 = sigmf(lo_f(pFA)) * cA0 + sigmf(lo_f(pIA)) * tanhfast(lo_f(pGA));
            hA0 = sigmf(lo_f(pOA)) * tanhfast(cA0);
            cA1 = sigmf(hi_f(pFA)) * cA1 + sigmf(hi_f(pIA)) * tanhfast(hi_f(pGA));
            hA1 = sigmf(hi_f(pOA)) * tanhfast(cA1);
            cB0 = sigmf(lo_f(pFB)) * cB0 + sigmf(lo_f(pIB)) * tanhfast(lo_f(pGB));
            hB0 = sigmf(lo_f(pOB)) * tanhfast(cB0);
            cB1 = sigmf(hi_f(pFB)) * cB1 + sigmf(hi_f(pIB)) * tanhfast(hi_f(pGB));
            hB1 = sigmf(hi_f(pOB)) * tanhfast(cB1);
        }
        // next W1 orders per-warp workspace rewrites against this iteration.
    }

    // ---- output head + loss reduce (even warp of each pair) ----
    float yLA = 0.f, tLA = 0.f, yLB = 0.f, tLB = 0.f;
    float yA = 0.f, yB = 0.f;
    if (isEven) {
        yA = sOutW[2 * lane] * hA0 + sOutW[2 * lane + 1] * hA1;
        yB = sOutW[2 * lane] * hB0 + sOutW[2 * lane + 1] * hB1;
#pragma unroll
        for (int o = 16; o; o >>= 1) {
            yA += __shfl_xor_sync(0xffffffffu, yA, o);
            yB += __shfl_xor_sync(0xffffffffu, yB, o);
            lossAcc += __shfl_xor_sync(0xffffffffu, lossAcc, o);
        }
        if (lane == 0) {
            float ob = out_b[0];
            float ya = yA + ob, yb = yB + ob;
            out_pred[b0 + rowA] = sigmf(ya);
            out_pred[b0 + rowB] = sigmf(yb);
            float labA = labels[b0 + rowA], itrA = is_train[b0 + rowA];
            float labB = labels[b0 + rowB], itrB = is_train[b0 + rowB];
            float mvA = fmaxf(-ya, 0.f);
            float bceA = ya - ya * labA + mvA + __logf(__expf(-mvA) + __expf(-ya - mvA));
            float mvB = fmaxf(-yb, 0.f);
            float bceB = yb - yb * labB + mvB + __logf(__expf(-mvB) + __expf(-yb - mvB));
            yLA = bceA * itrA; tLA = itrA;
            yLB = bceB * itrB; tLB = itrB;
        }
    }
    __syncthreads();
    if (isEven && lane == 0) {
        sRed[pair] = lossAcc;           // pair's lossAcc covers both rows
        sRed[8 + rowA] = yLA; sRed[8 + rowB] = yLB;
        sRed[16 + rowA] = tLA; sRed[16 + rowB] = tLB;
    }
    __syncthreads();
    if (tid == 0) {
        float xl = 0.f, ys = 0.f, ts = 0.f;
#pragma unroll
        for (int i = 0; i < 4; i++) xl += sRed[i];
#pragma unroll
        for (int i = 0; i < 8; i++) { ys += sRed[8 + i]; ts += sRed[16 + i]; }
        gXloss[blockIdx.x] = xl;
        gYsum[blockIdx.x]  = ys;
        gTsum[blockIdx.x]  = ts;
    }
}

// ---------------------------------------------------------------------------
// K3: deterministic final combine
// ---------------------------------------------------------------------------
__global__ void k_final(float* __restrict__ out) {
    float xl = 0.f, ys = 0.f, ts = 0.f;
    for (int i = 0; i < NBLK; i++) { xl += gXloss[i]; ys += gYsum[i]; ts += gTsum[i]; }
    out[0] = xl / (float)TT + 0.1f * (ys / (ts + 1e-5f));
}

extern "C" void kernel_launch(void* const* d_in, const int* in_sizes, int n_in,
                              void* d_out, int out_size) {
    const float* values   = (const float*)d_in[0];
    const float* masks    = (const float*)d_in[1];
    const float* deltas   = (const float*)d_in[2];
    // d_in[3] evals, d_in[4] eval_masks: unused by the forward outputs
    const float* labels   = (const float*)d_in[5];
    const float* is_train = (const float*)d_in[6];
    const float* td_h_W   = (const float*)d_in[7];
    const float* td_h_b   = (const float*)d_in[8];
    const float* td_x_W   = (const float*)d_in[9];
    const float* td_x_b   = (const float*)d_in[10];
    const float* hist_W   = (const float*)d_in[11];
    const float* hist_b   = (const float*)d_in[12];
    const float* feat_W   = (const float*)d_in[13];
    const float* feat_b   = (const float*)d_in[14];
    const float* wc_W     = (const float*)d_in[15];
    const float* wc_b     = (const float*)d_in[16];
    const float* W_ih     = (const float*)d_in[17];
    const float* W_hh     = (const float*)d_in[18];
    const float* b_ih     = (const float*)d_in[19];
    const float* b_hh     = (const float*)d_in[20];
    const float* out_W    = (const float*)d_in[21];
    const float* out_b    = (const float*)d_in[22];
    float* out = (float*)d_out;

    cudaFuncSetAttribute(k_main, cudaFuncAttributeMaxDynamicSharedMemorySize, SMEM_BYTES);

    // out layout: [loss(1) | predictions(B) | imputations(B*T*N)]
    k_msum<<<TT, 256>>>(masks);
    k_main<<<NBLK, NTHR, SMEM_BYTES>>>(values, masks, deltas, labels, is_train,
                                       td_h_W, td_h_b, td_x_W, td_x_b,
                                       hist_W, hist_b, feat_W, feat_b,
                                       wc_W, wc_b, W_ih, W_hh, b_ih, b_hh,
                                       out_W, out_b,
                                       out + 1, out + 1 + BB);
    k_final<<<1, 1>>>(out);
}